// round 1
// baseline (speedup 1.0000x reference)
#include <cuda_runtime.h>
#include <math.h>

#define BC     4
#define NODES  4096
#define FEAT   64
#define OUTD   32
#define NEDGES (32 * NODES)
#define NW     (NODES / 32)   // 128 bitmap words per row

// Scratch (no allocations allowed in kernel_launch)
__device__ float    g_z[BC * NODES * OUTD];   // 2 MB: z = h @ W
__device__ unsigned g_bits[NODES * NW];       // 2 MB: dedup'd adjacency bitmap
__device__ float    g_zsum[BC * OUTD];        // column sums of z (fallback row)

// ---------------------------------------------------------------------------
__global__ void k_clear() {
    int i = blockIdx.x * blockDim.x + threadIdx.x;
    const int n = NODES * NW;
    for (; i < n; i += gridDim.x * blockDim.x) g_bits[i] = 0u;
}

__global__ void k_setbits(const int* __restrict__ row, const int* __restrict__ col) {
    int i = blockIdx.x * blockDim.x + threadIdx.x;
    if (i < NEDGES) {
        int r = row[i], c = col[i];
        atomicOr(&g_bits[r * NW + (c >> 5)], 1u << (c & 31));
    }
}

// z[r, d] = sum_f h[r, f] * W[f, d]   (one warp per row; r spans BC*NODES)
__global__ void k_z(const float* __restrict__ h, const float* __restrict__ W) {
    int lane = threadIdx.x & 31;
    int r = blockIdx.x * (blockDim.x >> 5) + (threadIdx.x >> 5);
    const float* hr = h + (long)r * FEAT;
    float acc = 0.f;
#pragma unroll
    for (int f = 0; f < FEAT; f++)
        acc = fmaf(hr[f], W[f * OUTD + lane], acc);
    g_z[r * OUTD + lane] = acc;
}

// g_zsum[b, d] = sum_n z[b, n, d]
__global__ void k_zsum() {
    int b = blockIdx.x;
    int t = threadIdx.x;
    int d = t & 31, part = t >> 5;           // 8 partial accumulators per d
    float s = 0.f;
    for (int n = part; n < NODES; n += 8)
        s += g_z[(b * NODES + n) * OUTD + d];
    __shared__ float red[256];
    red[t] = s;
    __syncthreads();
    if (part == 0) {
        float tot = 0.f;
#pragma unroll
        for (int p = 0; p < 8; p++) tot += red[p * 32 + d];
        g_zsum[b * OUTD + d] = tot;
    }
}

// ---------------------------------------------------------------------------
// Main kernel: one block per destination row. Scan bitmap row once (shared
// across batches), build deterministic neighbor list, then per batch run a
// 4-warp online softmax + weighted aggregation over the neighbors.
__global__ __launch_bounds__(128) void k_gat(float* __restrict__ out) {
    __shared__ unsigned short nbr[NODES];    // worst-case full row
    __shared__ int   s_wtot[4];
    __shared__ float s_m[4], s_sum[4], s_acc[4][32];

    const int row  = blockIdx.x;
    const int tid  = threadIdx.x;
    const int lane = tid & 31, wid = tid >> 5;

    // --- Phase A: deterministic neighbor-list build from bitmap ---
    unsigned w = g_bits[row * NW + tid];
    int cnt = __popc(w);
    int v = cnt;                              // warp inclusive scan
#pragma unroll
    for (int o = 1; o < 32; o <<= 1) {
        int t = __shfl_up_sync(0xffffffffu, v, o);
        if (lane >= o) v += t;
    }
    if (lane == 31) s_wtot[wid] = v;
    __syncthreads();
    int base = 0;
#pragma unroll
    for (int k = 0; k < 4; k++) if (k < wid) base += s_wtot[k];
    const int M = s_wtot[0] + s_wtot[1] + s_wtot[2] + s_wtot[3];
    int off = base + v - cnt;                 // exclusive offset for this word
    unsigned ww = w;
    while (ww) {
        int b = __ffs(ww) - 1;
        nbr[off++] = (unsigned short)(tid * 32 + b);
        ww &= ww - 1;
    }
    __syncthreads();

    // --- Phase B: per batch, online softmax over neighbors ---
    for (int b = 0; b < BC; b++) {
        const float* zb = g_z + b * NODES * OUTD;
        const float  zi = zb[row * OUTD + lane];   // broadcast row z_i[lane]

        float m = -INFINITY, ssum = 0.f, acc = 0.f;
        for (int k = wid; k < M; k += 4) {
            int   j  = nbr[k];
            float zj = zb[j * OUTD + lane];
            float p  = zi * zj;
#pragma unroll
            for (int o = 16; o; o >>= 1) p += __shfl_xor_sync(0xffffffffu, p, o);
            float s = (p >= 0.f) ? p : 0.1f * p;   // LeakyReLU(0.1)
            if (s != 0.f) {                        // att==0 -> masked (-1e16 -> exp underflow 0)
                float nm = fmaxf(m, s);
                float c  = __expf(m - nm);         // m=-inf -> 0 (first valid)
                float e  = __expf(s - nm);
                ssum = ssum * c + e;
                acc  = acc  * c + e * zj;
                m = nm;
            }
        }
        if (lane == 0) { s_m[wid] = m; s_sum[wid] = ssum; }
        s_acc[wid][lane] = acc;
        __syncthreads();

        if (wid == 0) {
            float gm = fmaxf(fmaxf(s_m[0], s_m[1]), fmaxf(s_m[2], s_m[3]));
            float o;
            if (gm > -INFINITY) {
                float tot = 0.f, a = 0.f;
#pragma unroll
                for (int u = 0; u < 4; u++) {
                    if (s_m[u] > -INFINITY) {
                        float c = __expf(s_m[u] - gm);
                        tot += s_sum[u] * c;
                        a   += s_acc[u][lane] * c;
                    }
                }
                o = a / tot;
            } else {
                // fully-masked row: softmax is uniform over ALL 4096 columns
                o = g_zsum[b * OUTD + lane] * (1.f / (float)NODES);
            }
            out[(b * NODES + row) * OUTD + lane] = o;
        }
        __syncthreads();  // protect s_m/s_sum/s_acc before next batch
    }
}

// ---------------------------------------------------------------------------
extern "C" void kernel_launch(void* const* d_in, const int* in_sizes, int n_in,
                              void* d_out, int out_size) {
    const float* h       = (const float*)d_in[0];
    const float* W       = (const float*)d_in[1];
    const int*   adj_row = (const int*)d_in[2];
    const int*   adj_col = (const int*)d_in[3];
    float*       out     = (float*)d_out;

    k_clear  <<<512, 256>>>();
    k_setbits<<<(NEDGES + 255) / 256, 256>>>(adj_row, adj_col);
    k_z      <<<(BC * NODES) / 8, 256>>>(h, W);
    k_zsum   <<<BC, 256>>>();
    k_gat    <<<NODES, 128>>>(out);
}

// round 2
// speedup vs baseline: 1.6830x; 1.6830x over previous
#include <cuda_runtime.h>
#include <math.h>

#define BC     4
#define NODES  4096
#define FEAT   64
#define OUTD   32
#define NEDGES (32 * NODES)
#define NW     (NODES / 32)   // 128 bitmap words per row

// Scratch (no allocations allowed in kernel_launch)
__device__ float    g_z[BC * NODES * OUTD];   // 2 MB: z = h @ W
__device__ unsigned g_bits[NODES * NW];       // 2 MB: dedup'd adjacency bitmap
__device__ float    g_zsum[BC * OUTD];        // column sums of z (fallback row)

// ---------------------------------------------------------------------------
__global__ void k_clear() {
    int i = blockIdx.x * blockDim.x + threadIdx.x;
    const int n = NODES * NW;
    if (i < BC * OUTD) g_zsum[i] = 0.f;
    for (; i < n; i += gridDim.x * blockDim.x) g_bits[i] = 0u;
}

__global__ void k_setbits(const int* __restrict__ row, const int* __restrict__ col) {
    int i = blockIdx.x * blockDim.x + threadIdx.x;
    if (i < NEDGES) {
        int r = row[i], c = col[i];
        atomicOr(&g_bits[r * NW + (c >> 5)], 1u << (c & 31));
    }
}

// z[r, d] = sum_f h[r, f] * W[f, d]   (one warp per row; 8 warps per block)
// Fused: block-level partial column sums -> atomicAdd into g_zsum.
// NODES % 8 == 0, so every block lies entirely within one batch.
__global__ __launch_bounds__(256) void k_z(const float* __restrict__ h,
                                           const float* __restrict__ W) {
    const int lane = threadIdx.x & 31, wid = threadIdx.x >> 5;
    const int r = blockIdx.x * 8 + wid;
    const float* hr = h + (long)r * FEAT;
    float acc = 0.f;
#pragma unroll
    for (int f = 0; f < FEAT; f++)
        acc = fmaf(hr[f], W[f * OUTD + lane], acc);
    g_z[r * OUTD + lane] = acc;

    __shared__ float red[8][OUTD];
    red[wid][lane] = acc;
    __syncthreads();
    if (wid == 0) {
        float s = 0.f;
#pragma unroll
        for (int p = 0; p < 8; p++) s += red[p][lane];
        const int b = (blockIdx.x * 8) / NODES;
        atomicAdd(&g_zsum[b * OUTD + lane], s);
    }
}

// ---------------------------------------------------------------------------
// Main kernel: one block per destination row, one WARP per BATCH.
// Phase A (all 4 warps): scan 512B bitmap row once, build deterministic
// neighbor list via prefix scan. Phase B: warp w runs the full online softmax
// + aggregation for batch w over the shared neighbor list.
__global__ __launch_bounds__(128) void k_gat(float* __restrict__ out) {
    __shared__ unsigned short nbr[NODES];    // worst-case full row
    __shared__ int s_wtot[4];

    const int row  = blockIdx.x;
    const int tid  = threadIdx.x;
    const int lane = tid & 31, wid = tid >> 5;

    // --- Phase A: deterministic neighbor-list build from bitmap ---
    unsigned w = g_bits[row * NW + tid];
    int cnt = __popc(w);
    int v = cnt;                              // warp inclusive scan
#pragma unroll
    for (int o = 1; o < 32; o <<= 1) {
        int t = __shfl_up_sync(0xffffffffu, v, o);
        if (lane >= o) v += t;
    }
    if (lane == 31) s_wtot[wid] = v;
    __syncthreads();
    int base = 0;
#pragma unroll
    for (int k = 0; k < 4; k++) if (k < wid) base += s_wtot[k];
    const int M = s_wtot[0] + s_wtot[1] + s_wtot[2] + s_wtot[3];
    int off = base + v - cnt;                 // exclusive offset for this word
    unsigned ww = w;
    while (ww) {
        int b = __ffs(ww) - 1;
        nbr[off++] = (unsigned short)(tid * 32 + b);
        ww &= ww - 1;
    }
    __syncthreads();

    // --- Phase B: warp `wid` processes batch `wid` end-to-end ---
    const float* zb = g_z + wid * NODES * OUTD;
    const float  zi = zb[row * OUTD + lane];  // z_i[lane] for this batch

    float m = -INFINITY, ssum = 0.f, acc = 0.f;
    for (int k = 0; k < M; k++) {
        const int   j  = nbr[k];
        const float zj = zb[j * OUTD + lane];
        float p = zi * zj;
#pragma unroll
        for (int o = 16; o; o >>= 1) p += __shfl_xor_sync(0xffffffffu, p, o);
        const float s = (p >= 0.f) ? p : 0.1f * p;   // LeakyReLU(0.1)
        if (s != 0.f) {                // att==0 -> masked (-1e16 -> exp -> 0)
            const float nm = fmaxf(m, s);
            const float c  = __expf(m - nm);         // m=-inf -> 0 on first hit
            const float e  = __expf(s - nm);
            ssum = ssum * c + e;
            acc  = acc  * c + e * zj;
            m = nm;
        }
    }

    float o;
    if (m > -INFINITY) {
        o = acc / ssum;
    } else {
        // fully-masked row: softmax uniform over ALL 4096 columns
        o = g_zsum[wid * OUTD + lane] * (1.f / (float)NODES);
    }
    out[(wid * NODES + row) * OUTD + lane] = o;
}

// ---------------------------------------------------------------------------
extern "C" void kernel_launch(void* const* d_in, const int* in_sizes, int n_in,
                              void* d_out, int out_size) {
    const float* h       = (const float*)d_in[0];
    const float* W       = (const float*)d_in[1];
    const int*   adj_row = (const int*)d_in[2];
    const int*   adj_col = (const int*)d_in[3];
    float*       out     = (float*)d_out;

    k_clear  <<<512, 256>>>();
    k_setbits<<<(NEDGES + 255) / 256, 256>>>(adj_row, adj_col);
    k_z      <<<(BC * NODES) / 8, 256>>>(h, W);
    k_gat    <<<NODES, 128>>>(out);
}

// round 3
// speedup vs baseline: 1.7106x; 1.0164x over previous
#include <cuda_runtime.h>
#include <math.h>

#define BC     4
#define NODES  4096
#define FEAT   64
#define OUTD   32
#define NEDGES (32 * NODES)
#define NW     (NODES / 32)   // 128 bitmap words per row

// Scratch (no allocations allowed in kernel_launch)
__device__ float    g_z[BC * NODES * OUTD];   // 2 MB: z = h @ W
__device__ unsigned g_bits[NODES * NW];       // 2 MB: dedup'd adjacency bitmap

// ---------------------------------------------------------------------------
// Fused: z = h @ W (one warp per row, 8 warps/block) AND clear the bitmap.
// grid = BC*NODES/8 = 2048 blocks; 2048*256 threads == NODES*NW words.
__global__ __launch_bounds__(256) void k_z_clear(const float* __restrict__ h,
                                                 const float* __restrict__ W) {
    const int tid = threadIdx.x;
    g_bits[blockIdx.x * 256 + tid] = 0u;      // independent of z work

    const int lane = tid & 31, wid = tid >> 5;
    const int r = blockIdx.x * 8 + wid;
    const float* hr = h + (long)r * FEAT;
    float acc = 0.f;
#pragma unroll
    for (int f = 0; f < FEAT; f++)
        acc = fmaf(hr[f], W[f * OUTD + lane], acc);
    g_z[r * OUTD + lane] = acc;
}

__global__ void k_setbits(const int* __restrict__ row, const int* __restrict__ col) {
    int i = blockIdx.x * blockDim.x + threadIdx.x;
    if (i < NEDGES) {
        int r = row[i], c = col[i];
        atomicOr(&g_bits[r * NW + (c >> 5)], 1u << (c & 31));
    }
}

// ---------------------------------------------------------------------------
// One block per destination row; warp w owns batch w.
// Phase A: deterministic neighbor list from the bitmap (shared across warps).
// Phase B: 32-neighbor tiles — lane = neighbor for scoring (parallel dots from
// shared), lane = feature for staging/aggregation. One butterfly per tile.
__global__ __launch_bounds__(128) void k_gat(float* __restrict__ out) {
    __shared__ unsigned short nbr[NODES];     // worst-case full row
    __shared__ int   s_wtot[4];
    __shared__ float tile[4][32][33];         // [warp][nbr-in-tile][d], padded

    const int row  = blockIdx.x;
    const int tid  = threadIdx.x;
    const int lane = tid & 31, wid = tid >> 5;

    // --- Phase A: neighbor-list build ---
    unsigned w = g_bits[row * NW + tid];
    int cnt = __popc(w);
    int v = cnt;
#pragma unroll
    for (int o = 1; o < 32; o <<= 1) {
        int t = __shfl_up_sync(0xffffffffu, v, o);
        if (lane >= o) v += t;
    }
    if (lane == 31) s_wtot[wid] = v;
    __syncthreads();
    int base = 0;
#pragma unroll
    for (int k = 0; k < 4; k++) if (k < wid) base += s_wtot[k];
    const int M = s_wtot[0] + s_wtot[1] + s_wtot[2] + s_wtot[3];
    int off = base + v - cnt;
    unsigned ww = w;
    while (ww) {
        int b = __ffs(ww) - 1;
        nbr[off++] = (unsigned short)(tid * 32 + b);
        ww &= ww - 1;
    }
    __syncthreads();

    // --- Phase B: warp `wid` = batch `wid` ---
    const float* zb = g_z + wid * NODES * OUTD;
    const float  zi = zb[row * OUTD + lane];      // lane = feature d

    float m = -INFINITY, ssum = 0.f;
    float acc0 = 0.f, acc1 = 0.f;                 // split FMA chains

    for (int t = 0; t < M; t += 32) {
        // this lane's neighbor for the tile (tail lanes duplicate M-1; masked)
        const int  idx = t + lane;
        const int  j   = nbr[(idx < M) ? idx : (M - 1)];

        // stage 32 z_j rows, coalesced over lane=d
#pragma unroll 8
        for (int k = 0; k < 32; k++) {
            int jk = __shfl_sync(0xffffffffu, j, k);
            tile[wid][k][lane] = zb[jk * OUTD + lane];
        }
        __syncwarp();

        // score for this lane's neighbor: dot(z_i, tile[lane][:])
        float d0 = 0.f, d1 = 0.f;
#pragma unroll
        for (int d = 0; d < 32; d += 2) {
            d0 = fmaf(tile[wid][lane][d],     __shfl_sync(0xffffffffu, zi, d),     d0);
            d1 = fmaf(tile[wid][lane][d + 1], __shfl_sync(0xffffffffu, zi, d + 1), d1);
        }
        const float p = d0 + d1;
        const float s = (p >= 0.f) ? p : 0.1f * p;        // LeakyReLU(0.1)
        const bool  valid = (idx < M) && (s != 0.f);      // att==0 -> masked
        const float sv = valid ? s : -INFINITY;

        // one butterfly max per 32 neighbors
        float tm = sv;
#pragma unroll
        for (int o = 16; o; o >>= 1) tm = fmaxf(tm, __shfl_xor_sync(0xffffffffu, tm, o));
        const float nm = fmaxf(m, tm);

        if (nm > -INFINITY) {                              // warp-uniform
            const float corr = __expf(m - nm);             // 0 when m == -inf
            const float e = valid ? __expf(sv - nm) : 0.f;
            float esum = e;
#pragma unroll
            for (int o = 16; o; o >>= 1) esum += __shfl_xor_sync(0xffffffffu, esum, o);
            ssum = ssum * corr + esum;
            acc0 *= corr;  acc1 *= corr;
#pragma unroll 8
            for (int k = 0; k < 32; k += 2) {
                acc0 = fmaf(__shfl_sync(0xffffffffu, e, k),     tile[wid][k][lane],     acc0);
                acc1 = fmaf(__shfl_sync(0xffffffffu, e, k + 1), tile[wid][k + 1][lane], acc1);
            }
            m = nm;
        }
        __syncwarp();   // staging of next tile must not overrun reads
    }

    float o;
    if (m > -INFINITY) {
        o = (acc0 + acc1) / ssum;
    } else {
        // fully-masked row: softmax uniform over ALL 4096 columns.
        // (probability ~e^-32; compute column sum on demand)
        float s2 = 0.f;
        for (int n = 0; n < NODES; n++) s2 += zb[n * OUTD + lane];
        o = s2 * (1.f / (float)NODES);
    }
    out[(wid * NODES + row) * OUTD + lane] = o;
}

// ---------------------------------------------------------------------------
extern "C" void kernel_launch(void* const* d_in, const int* in_sizes, int n_in,
                              void* d_out, int out_size) {
    const float* h       = (const float*)d_in[0];
    const float* W       = (const float*)d_in[1];
    const int*   adj_row = (const int*)d_in[2];
    const int*   adj_col = (const int*)d_in[3];
    float*       out     = (float*)d_out;

    k_z_clear<<<(BC * NODES) / 8, 256>>>(h, W);
    k_setbits<<<(NEDGES + 255) / 256, 256>>>(adj_row, adj_col);
    k_gat    <<<NODES, 128>>>(out);
}

// round 4
// speedup vs baseline: 2.0824x; 1.2174x over previous
#include <cuda_runtime.h>
#include <math.h>

#define BC     4
#define NODES  4096
#define FEAT   64
#define OUTD   32
#define NEDGES (32 * NODES)
#define NW     (NODES / 32)   // 128 bitmap words per row

// Scratch (no allocations allowed in kernel_launch)
__device__ float    g_z[BC * NODES * OUTD];   // 2 MB: z = h @ W
__device__ unsigned g_bits[NODES * NW];       // 2 MB: dedup'd adjacency bitmap

// ---------------------------------------------------------------------------
// Fused: z = h @ W (one warp per 4 rows -> W loaded once, 4 FMA chains)
// AND clear the bitmap. grid = 512 blocks of 256 threads.
__global__ __launch_bounds__(256) void k_z_clear(const float* __restrict__ h,
                                                 const float* __restrict__ W) {
    const int tid = threadIdx.x;
#pragma unroll
    for (int i = 0; i < 4; i++)               // 512*256*4 == NODES*NW
        g_bits[(blockIdx.x * 4 + i) * 256 + tid] = 0u;

    const int lane = tid & 31, wid = tid >> 5;
    const int r0 = (blockIdx.x * 8 + wid) * 4;     // 4 consecutive rows
    const float* hr = h + (long)r0 * FEAT;
    float a0 = 0.f, a1 = 0.f, a2 = 0.f, a3 = 0.f;
#pragma unroll 16
    for (int f = 0; f < FEAT; f++) {
        const float wv = W[f * OUTD + lane];       // loaded ONCE per 4 rows
        a0 = fmaf(hr[f],            wv, a0);
        a1 = fmaf(hr[FEAT + f],     wv, a1);
        a2 = fmaf(hr[2 * FEAT + f], wv, a2);
        a3 = fmaf(hr[3 * FEAT + f], wv, a3);
    }
    g_z[(r0 + 0) * OUTD + lane] = a0;
    g_z[(r0 + 1) * OUTD + lane] = a1;
    g_z[(r0 + 2) * OUTD + lane] = a2;
    g_z[(r0 + 3) * OUTD + lane] = a3;
}

__global__ void k_setbits(const int* __restrict__ row, const int* __restrict__ col) {
    int i = blockIdx.x * blockDim.x + threadIdx.x;
    if (i < NEDGES) {
        int r = row[i], c = col[i];
        atomicOr(&g_bits[r * NW + (c >> 5)], 1u << (c & 31));
    }
}

// ---------------------------------------------------------------------------
// One block per destination row; warp w owns batch w.
// Tile layout: 32 neighbor rows x 36 floats (9 float4, pad for bank-freedom):
//   STS.128 staging  : lanes hit distinct bank-groups per 8-lane phase
//   LDS.128 row read : conflict-free in 4 phases
//   scalar col read  : (k*36 + lane) % 32 distinct across lanes
#define TPAD 36
__global__ __launch_bounds__(128) void k_gat(float* __restrict__ out) {
    __shared__ unsigned short nbr[NODES];
    __shared__ int   s_wtot[4];
    __shared__ __align__(16) float tile[4][32 * TPAD];
    __shared__ float s_zi[4][32];
    __shared__ float s_e[4][32];

    const int row  = blockIdx.x;
    const int tid  = threadIdx.x;
    const int lane = tid & 31, wid = tid >> 5;

    // --- Phase A: deterministic neighbor-list build from bitmap ---
    unsigned w = g_bits[row * NW + tid];
    int cnt = __popc(w);
    int v = cnt;
#pragma unroll
    for (int o = 1; o < 32; o <<= 1) {
        int t = __shfl_up_sync(0xffffffffu, v, o);
        if (lane >= o) v += t;
    }
    if (lane == 31) s_wtot[wid] = v;
    __syncthreads();
    int base = 0;
#pragma unroll
    for (int k = 0; k < 4; k++) if (k < wid) base += s_wtot[k];
    const int M = s_wtot[0] + s_wtot[1] + s_wtot[2] + s_wtot[3];
    int off = base + v - cnt;
    unsigned ww = w;
    while (ww) {
        int b = __ffs(ww) - 1;
        nbr[off++] = (unsigned short)(tid * 32 + b);
        ww &= ww - 1;
    }
    __syncthreads();

    // --- Phase B: warp `wid` = batch `wid` ---
    const float*  zb  = g_z + wid * NODES * OUTD;
    const float4* zb4 = (const float4*)zb;        // 8 float4 per node row
    float*  tw  = tile[wid];
    float4* tw4 = (float4*)tw;

    const float zi = zb[row * OUTD + lane];
    s_zi[wid][lane] = zi;
    __syncwarp();

    float m = -INFINITY, ssum = 0.f;
    float acc0 = 0.f, acc1 = 0.f;

    for (int t = 0; t < M; t += 32) {
        const int idx   = t + lane;
        const bool inr  = (idx < M);
        const int j     = nbr[inr ? idx : (M - 1)];

        // stage 32 rows: 8 x (shfl + LDG.128 + STS.128)
#pragma unroll
        for (int i = 0; i < 8; i++) {
            const int e  = i * 32 + lane;          // 0..255
            const int k  = e >> 3, d4 = e & 7;
            const int jk = __shfl_sync(0xffffffffu, j, k);
            tw4[k * 9 + d4] = zb4[jk * 8 + d4];
        }
        __syncwarp();

        // score for this lane's neighbor: dot(z_i, tile[lane][:])
        float d0 = 0.f, d1 = 0.f;
#pragma unroll
        for (int i = 0; i < 8; i++) {
            const float4 vv = tw4[lane * 9 + i];
            d0 = fmaf(vv.x, s_zi[wid][4 * i + 0], d0);
            d1 = fmaf(vv.y, s_zi[wid][4 * i + 1], d1);
            d0 = fmaf(vv.z, s_zi[wid][4 * i + 2], d0);
            d1 = fmaf(vv.w, s_zi[wid][4 * i + 3], d1);
        }
        const float p = d0 + d1;
        const float s = (p >= 0.f) ? p : 0.1f * p;        // LeakyReLU(0.1)
        const bool  valid = inr && (s != 0.f);            // att==0 -> masked
        const float sv = valid ? s : -INFINITY;

        float tm = sv;
#pragma unroll
        for (int o = 16; o; o >>= 1) tm = fmaxf(tm, __shfl_xor_sync(0xffffffffu, tm, o));
        const float nm = fmaxf(m, tm);

        if (nm > -INFINITY) {                              // warp-uniform
            const float corr = __expf(m - nm);             // 0 when m == -inf
            const float e = valid ? __expf(sv - nm) : 0.f;
            float esum = e;
#pragma unroll
            for (int o = 16; o; o >>= 1) esum += __shfl_xor_sync(0xffffffffu, esum, o);
            ssum = ssum * corr + esum;
            s_e[wid][lane] = e;
            acc0 *= corr;  acc1 *= corr;
            __syncwarp();
#pragma unroll 8
            for (int k = 0; k < 32; k += 2) {
                acc0 = fmaf(s_e[wid][k],     tw[k * TPAD + lane],       acc0);
                acc1 = fmaf(s_e[wid][k + 1], tw[(k + 1) * TPAD + lane], acc1);
            }
            m = nm;
        }
        __syncwarp();
    }

    float o;
    if (m > -INFINITY) {
        o = (acc0 + acc1) / ssum;
    } else {
        // fully-masked row: softmax uniform over ALL 4096 columns
        float s2 = 0.f;
        for (int n = 0; n < NODES; n++) s2 += zb[n * OUTD + lane];
        o = s2 * (1.f / (float)NODES);
    }
    out[(wid * NODES + row) * OUTD + lane] = o;
}

// ---------------------------------------------------------------------------
extern "C" void kernel_launch(void* const* d_in, const int* in_sizes, int n_in,
                              void* d_out, int out_size) {
    const float* h       = (const float*)d_in[0];
    const float* W       = (const float*)d_in[1];
    const int*   adj_row = (const int*)d_in[2];
    const int*   adj_col = (const int*)d_in[3];
    float*       out     = (float*)d_out;

    k_z_clear<<<(BC * NODES) / 32, 256>>>(h, W);
    k_setbits<<<(NEDGES + 255) / 256, 256>>>(adj_row, adj_col);
    k_gat    <<<NODES, 128>>>(out);
}